// round 3
// baseline (speedup 1.0000x reference)
#include <cuda_runtime.h>
#include <math.h>

#define C        144
#define W        77
#define KW       10
#define FC       64
#define CONV_OUT 68                    // W - KW + 1
#define CONCAT   (C*FC + CONV_OUT)     // 9284
#define H2       128
#define NSPLIT   2                     // blocks per channel
#define HALF_FC  (FC / NSPLIT)         // 32 columns per block
#define GRID     (C * NSPLIT + 1)      // 289: 288 FC blocks + 1 conv block

// Scratch (no device allocation allowed); zero-initialized at module load,
// reset by the last block each run so graph replays stay correct.
__device__ __align__(16) float g_h[H2];
__device__ unsigned int g_cnt = 0u;

__device__ __forceinline__ float warp_reduce(float v) {
#pragma unroll
    for (int o = 16; o > 0; o >>= 1) v += __shfl_down_sync(0xffffffffu, v, o);
    return v;
}

// ---------------------------------------------------------------------------
// Barrier-free fused kernel.
//   Blocks 0..287: block (c, half) computes 32 FC outputs of channel c and
//     immediately accumulates W2[:, cols] * fc_out[cols] into g_h via atomics.
//   Block 288: computes conv[68] and accumulates W2[:, 9216:9284] * conv.
//   Last block to finish (atomic counter) runs the tiny final layer:
//     out = sigmoid(relu(w3 . relu(g_h + b2) + b3)), then resets scratch.
// ---------------------------------------------------------------------------
__global__ __launch_bounds__(256) void fused_kernel(
    const float* __restrict__ x,       // [C, W]
    const float* __restrict__ fc_w,    // [C, FC, W]
    const float* __restrict__ fc_b,    // [C, FC]
    const float* __restrict__ conv_w,  // [C, KW]
    const float* __restrict__ conv_b,  // [1]
    const float* __restrict__ w2,      // [H2, CONCAT]
    const float* __restrict__ b2,      // [H2]
    const float* __restrict__ w3,      // [1, H2]
    const float* __restrict__ b3,      // [1]
    float* __restrict__ out)           // [1]
{
    const int tid  = threadIdx.x;
    const int lane = tid & 31;
    const int warp = tid >> 5;
    const int b    = blockIdx.x;

    __shared__ float sh[C * KW];                 // conv weights / xs reuse
    __shared__ __align__(16) float vals[CONV_OUT]; // fc_out slice or conv slice
    __shared__ float part[8][CONV_OUT];
    __shared__ float red[8];
    __shared__ unsigned int s_last;

    if (b < C * NSPLIT) {
        // ================= FC block: channel c, column half ================
        const int c    = b >> 1;
        const int half = b & 1;
        const int col0 = half * HALF_FC;         // 0 or 32 within channel

        // x row into shared
        if (tid < W) sh[tid] = x[c * W + tid];
        __syncthreads();

        // 8 warps x 4 outputs: warp-reduced coalesced dots
#pragma unroll
        for (int i = 0; i < 4; i++) {
            const int dl = warp * 4 + i;                    // 0..31 local
            const float* row = fc_w + (size_t)(c * FC + col0 + dl) * W;
            float s = row[lane] * sh[lane] + row[lane + 32] * sh[lane + 32];
            if (lane < W - 64)
                s += row[lane + 64] * sh[lane + 64];
            s = warp_reduce(s);
            if (lane == 0) vals[dl] = s + fc_b[c * FC + col0 + dl];
        }
        __syncthreads();

        // Partial matvec: h[j] += w2[j, c*64+col0 .. +32] . vals[0..31]
        // 2 threads per row, 4 float4 each (16B-aligned: offsets are /4 clean)
        {
            const int j   = tid >> 1;            // 0..127
            const int sub = tid & 1;
            const float4* rw = reinterpret_cast<const float4*>(
                w2 + (size_t)j * CONCAT + c * FC + col0) + sub * 4;
            const float4* fv = reinterpret_cast<const float4*>(vals) + sub * 4;
            float s = 0.f;
#pragma unroll
            for (int q = 0; q < 4; q++) {
                const float4 a = rw[q];
                const float4 v = fv[q];
                s += a.x * v.x + a.y * v.y + a.z * v.z + a.w * v.w;
            }
            s += __shfl_xor_sync(0xffffffffu, s, 1);
            if (sub == 0) atomicAdd(&g_h[j], s);
        }
    } else {
        // ========================== conv block ============================
        for (int i = tid; i < C * KW; i += 256) sh[i] = conv_w[i];
        __syncthreads();

        float s0 = 0.f, s1 = 0.f, s2 = 0.f;      // outputs lane, +32, +64
        for (int ch = warp; ch < C; ch += 8) {
            const float* xr = x + ch * W;
#pragma unroll
            for (int k = 0; k < KW; k++) {
                const float wv = sh[ch * KW + k];
                s0 += xr[lane + k]      * wv;
                s1 += xr[lane + 32 + k] * wv;
                if (lane < CONV_OUT - 64)
                    s2 += xr[lane + 64 + k] * wv;
            }
        }
        part[warp][lane]      = s0;
        part[warp][lane + 32] = s1;
        if (lane < CONV_OUT - 64) part[warp][lane + 64] = s2;
        __syncthreads();

        if (tid < CONV_OUT) {
            float acc = conv_b[0];
#pragma unroll
            for (int wq = 0; wq < 8; wq++) acc += part[wq][tid];
            vals[tid] = acc;
        }
        __syncthreads();

        // Partial matvec: h[j] += w2[j, 9216:9284] . conv[0..67]
        if (tid < H2) {
            const int j = tid;
            const float4* rw = reinterpret_cast<const float4*>(
                w2 + (size_t)j * CONCAT + C * FC);   // 9216 floats -> 16B aligned
            const float4* cv = reinterpret_cast<const float4*>(vals);
            float s = 0.f;
#pragma unroll
            for (int q = 0; q < CONV_OUT / 4; q++) { // 17 float4s
                const float4 a = rw[q];
                const float4 v = cv[q];
                s += a.x * v.x + a.y * v.y + a.z * v.z + a.w * v.w;
            }
            atomicAdd(&g_h[j], s);
        }
    }

    // ----------------------- last-block finalization ----------------------
    __threadfence();                 // each thread: its g_h RED visible first
    __syncthreads();
    if (tid == 0)
        s_last = (atomicAdd(&g_cnt, 1u) == GRID - 1) ? 1u : 0u;
    __syncthreads();
    if (s_last == 0u) return;        // not last: exit, no spinning

    __threadfence();                 // acquire: see all blocks' g_h updates
    float v = 0.f;
    if (tid < H2)
        v = fmaxf(g_h[tid] + b2[tid], 0.f) * w3[tid];
    v = warp_reduce(v);
    if (lane == 0) red[warp] = v;
    __syncthreads();
    if (tid == 0) {
        float total = red[0] + red[1] + red[2] + red[3];
        const float o2 = fmaxf(total + b3[0], 0.f);
        out[0] = 1.f / (1.f + expf(-o2));
        g_cnt = 0u;                  // reset for next graph replay
    }
    __syncthreads();
    if (tid < H2) g_h[tid] = 0.f;    // reset accumulator for next replay
}

// ---------------------------------------------------------------------------
extern "C" void kernel_launch(void* const* d_in, const int* in_sizes, int n_in,
                              void* d_out, int out_size) {
    const float* x      = (const float*)d_in[0];
    const float* fc_w   = (const float*)d_in[1];
    const float* fc_b   = (const float*)d_in[2];
    const float* conv_w = (const float*)d_in[3];
    const float* conv_b = (const float*)d_in[4];
    const float* w2     = (const float*)d_in[5];
    const float* b2     = (const float*)d_in[6];
    const float* w3     = (const float*)d_in[7];
    const float* b3     = (const float*)d_in[8];

    fused_kernel<<<GRID, 256>>>(x, fc_w, fc_b, conv_w, conv_b,
                                w2, b2, w3, b3, (float*)d_out);
}

// round 4
// speedup vs baseline: 1.1186x; 1.1186x over previous
#include <cuda_runtime.h>
#include <math.h>

#define C        144
#define W        77
#define KW       10
#define FC       64
#define CONV_OUT 68                    // W - KW + 1
#define CONCAT   (C*FC + CONV_OUT)     // 9284
#define H2       128
#define GRID     C                     // one block per channel

// Scratch (no device allocation allowed); zeroed at load, reset by last block.
__device__ __align__(16) float g_h[H2];
__device__ __align__(16) float g_conv[CONV_OUT];
__device__ unsigned int g_cnt = 0u;

__device__ __forceinline__ float warp_reduce(float v) {
#pragma unroll
    for (int o = 16; o > 0; o >>= 1) v += __shfl_down_sync(0xffffffffu, v, o);
    return v;
}

// ---------------------------------------------------------------------------
// Barrier-free fused kernel, one block per channel.
//   Block c:
//     - FC: 64 outputs of channel c (warp-reduced dots, x in smem)
//     - conv: channel c's contribution to conv[68] -> atomicAdd g_conv
//     - h accumulate: g_h[j] += w2[j, c*64:(c+1)*64] . fc_vals   (coalesced,
//       w2 slice preloaded into registers before FC to overlap latency)
//   Last block (atomic counter): conv matvec (128x68) + final 2 layers,
//   then resets all scratch for the next graph replay.
// ---------------------------------------------------------------------------
__global__ __launch_bounds__(256) void fused_kernel(
    const float* __restrict__ x,       // [C, W]
    const float* __restrict__ fc_w,    // [C, FC, W]
    const float* __restrict__ fc_b,    // [C, FC]
    const float* __restrict__ conv_w,  // [C, KW]
    const float* __restrict__ conv_b,  // [1]
    const float* __restrict__ w2,      // [H2, CONCAT]
    const float* __restrict__ b2,      // [H2]
    const float* __restrict__ w3,      // [1, H2]
    const float* __restrict__ b3,      // [1]
    float* __restrict__ out)           // [1]
{
    const int tid  = threadIdx.x;
    const int lane = tid & 31;
    const int warp = tid >> 5;
    const int c    = blockIdx.x;

    __shared__ float xs[W];
    __shared__ float cw[KW];
    __shared__ __align__(16) float vals[FC];
    __shared__ __align__(16) float convv[CONV_OUT];
    __shared__ float sm_h[H2];
    __shared__ unsigned int s_last;

    // ---- stage 0: x row + conv weights into smem ----
    if (tid < W)                 xs[tid]     = x[c * W + tid];
    else if (tid < W + KW)       cw[tid - W] = conv_w[c * KW + (tid - W)];

    // ---- stage 1: preload this block's w2 slice into registers ----
    // 16 lanes per row: lanes {sub*16..sub*16+15} read row j = jj*16 + warp*2 + sub
    // columns c*64 .. c*64+63 (256 B contiguous -> coalesced).
    const int sub = lane >> 4;            // 0 or 1
    const int q   = lane & 15;            // float4 index within the 64-col slice
    float4 a[8];
#pragma unroll
    for (int jj = 0; jj < 8; jj++) {
        const int j = jj * 16 + warp * 2 + sub;          // 0..127
        a[jj] = *reinterpret_cast<const float4*>(
            w2 + (size_t)j * CONCAT + c * FC + q * 4);
    }

    __syncthreads();

    // ---- stage 2: conv contribution of channel c ----
    if (tid < CONV_OUT) {
        float s = 0.f;
#pragma unroll
        for (int k = 0; k < KW; k++) s += xs[tid + k] * cw[k];
        atomicAdd(&g_conv[tid], s);
    }

    // ---- stage 3: FC -- 8 warps x 8 outputs, warp-reduced dots ----
#pragma unroll
    for (int i = 0; i < 8; i++) {
        const int d = warp * 8 + i;                      // 0..63
        const float* row = fc_w + (size_t)(c * FC + d) * W;
        float s = row[lane] * xs[lane] + row[lane + 32] * xs[lane + 32];
        if (lane < W - 64)                               // 13 tail elements
            s += row[lane + 64] * xs[lane + 64];
        s = warp_reduce(s);
        if (lane == 0) vals[d] = s + fc_b[c * FC + d];
    }
    __syncthreads();

    // ---- stage 4: g_h[j] += w2_slice[j,:] . vals ----
    {
        const float4 vv = reinterpret_cast<const float4*>(vals)[q];
#pragma unroll
        for (int jj = 0; jj < 8; jj++) {
            float s = a[jj].x * vv.x + a[jj].y * vv.y
                    + a[jj].z * vv.z + a[jj].w * vv.w;
#pragma unroll
            for (int o = 8; o > 0; o >>= 1)
                s += __shfl_down_sync(0xffffffffu, s, o, 16);
            if (q == 0)
                atomicAdd(&g_h[jj * 16 + warp * 2 + sub], s);
        }
    }

    // ---- last-block election (no spinning; non-last blocks exit) ----
    __threadfence();
    __syncthreads();
    if (tid == 0)
        s_last = (atomicAdd(&g_cnt, 1u) == GRID - 1) ? 1u : 0u;
    __syncthreads();
    if (s_last == 0u) return;

    // =================== finalization (last block only) ===================
    __threadfence();                       // acquire all g_h / g_conv updates

    if (tid < CONV_OUT) {
        convv[tid]  = g_conv[tid] + conv_b[0];
        g_conv[tid] = 0.f;                 // reset for next replay
    }
    __syncthreads();

    // conv matvec: h[j] += w2[j, 9216:9284] . convv ; then relu & w3 weight
    {
        const int j2   = tid >> 1;
        const int sub2 = tid & 1;
        const float4* rw = reinterpret_cast<const float4*>(
            w2 + (size_t)j2 * CONCAT + C * FC);          // 16B-aligned
        const float4* cv = reinterpret_cast<const float4*>(convv);
        float s = 0.f;
#pragma unroll
        for (int qq = 0; qq < CONV_OUT / 4; qq++) {      // 17 float4
            if ((qq & 1) == sub2) {
                const float4 aw = rw[qq];
                const float4 vw = cv[qq];
                s += aw.x * vw.x + aw.y * vw.y + aw.z * vw.z + aw.w * vw.w;
            }
        }
        s += __shfl_xor_sync(0xffffffffu, s, 1);
        if (sub2 == 0) {
            const float pre = g_h[j2] + s + b2[j2];
            sm_h[j2] = fmaxf(pre, 0.f) * w3[j2];
            g_h[j2]  = 0.f;                // reset for next replay
        }
    }
    __syncthreads();

    if (warp == 0) {
        float v = sm_h[lane] + sm_h[lane + 32]
                + sm_h[lane + 64] + sm_h[lane + 96];
        v = warp_reduce(v);
        if (lane == 0) {
            const float o2 = fmaxf(v + b3[0], 0.f);
            out[0] = 1.f / (1.f + expf(-o2));
            g_cnt  = 0u;                   // reset for next replay
        }
    }
}

// ---------------------------------------------------------------------------
extern "C" void kernel_launch(void* const* d_in, const int* in_sizes, int n_in,
                              void* d_out, int out_size) {
    const float* x      = (const float*)d_in[0];
    const float* fc_w   = (const float*)d_in[1];
    const float* fc_b   = (const float*)d_in[2];
    const float* conv_w = (const float*)d_in[3];
    const float* conv_b = (const float*)d_in[4];
    const float* w2     = (const float*)d_in[5];
    const float* b2     = (const float*)d_in[6];
    const float* w3     = (const float*)d_in[7];
    const float* b3     = (const float*)d_in[8];

    fused_kernel<<<GRID, 256>>>(x, fc_w, fc_b, conv_w, conv_b,
                                w2, b2, w3, b3, (float*)d_out);
}

// round 5
// speedup vs baseline: 1.5761x; 1.4090x over previous
#include <cuda_runtime.h>
#include <math.h>

#define C        144
#define W        77
#define KW       10
#define FC       64
#define CONV_OUT 68                    // W - KW + 1
#define CONCAT   (C*FC + CONV_OUT)     // 9284
#define H2       128
#define GRID     C                     // one block per channel, 1 per SM
#define NT       1024                  // 32 warps per block

// Scratch (no device allocation allowed); zeroed at load, reset by last block.
__device__ __align__(16) float g_h[H2];
__device__ __align__(16) float g_conv[CONV_OUT];
__device__ unsigned int g_cnt = 0u;

__device__ __forceinline__ float warp_reduce(float v) {
#pragma unroll
    for (int o = 16; o > 0; o >>= 1) v += __shfl_down_sync(0xffffffffu, v, o);
    return v;
}

__device__ __forceinline__ float dot4(float4 a, float4 b) {
    return a.x * b.x + a.y * b.y + a.z * b.z + a.w * b.w;
}

// ---------------------------------------------------------------------------
// Barrier-free fused kernel, one 1024-thread block per channel (32 warps/SM).
//   Block c:
//     - preload w2[:, c*64:(c+1)*64] into registers (2 float4/thread, 8 th/row)
//     - FC: 64 outputs (32 warps x 2 outputs, warp-reduced dots, x in smem)
//     - conv: channel c's contribution -> atomicAdd g_conv[68]
//     - g_h[j] += w2_slice[j,:] . fc_vals  (8-lane group reduce + atomicAdd)
//   Last block (atomic counter): conv matvec (128x68) + final layers + reset.
// ---------------------------------------------------------------------------
__global__ __launch_bounds__(NT, 1) void fused_kernel(
    const float* __restrict__ x,       // [C, W]
    const float* __restrict__ fc_w,    // [C, FC, W]
    const float* __restrict__ fc_b,    // [C, FC]
    const float* __restrict__ conv_w,  // [C, KW]
    const float* __restrict__ conv_b,  // [1]
    const float* __restrict__ w2,      // [H2, CONCAT]
    const float* __restrict__ b2,      // [H2]
    const float* __restrict__ w3,      // [1, H2]
    const float* __restrict__ b3,      // [1]
    float* __restrict__ out)           // [1]
{
    const int tid  = threadIdx.x;
    const int lane = tid & 31;
    const int warp = tid >> 5;
    const int c    = blockIdx.x;

    const int j  = tid >> 3;           // 0..127 : w2 row owned by this thread
    const int p  = tid & 7;            // 0..7   : position within 8-thread row group

    __shared__ float xs[W];
    __shared__ float cw[KW];
    __shared__ __align__(16) float vals[FC];
    __shared__ __align__(16) float convv[CONV_OUT];
    __shared__ float sm_h[H2];
    __shared__ unsigned int s_last;

    // ---- stage 0: x row + conv weights into smem ----
    if (tid < W)               xs[tid]     = x[c * W + tid];
    else if (tid < W + KW)     cw[tid - W] = conv_w[c * KW + (tid - W)];

    // ---- stage 1: preload this block's w2 slice into registers ----
    // row j has 64 floats = 16 float4; 8 threads per row, 2 float4 each
    const float4* wrow = reinterpret_cast<const float4*>(
        w2 + (size_t)j * CONCAT + c * FC);
    const float4 a0 = wrow[p];
    const float4 a1 = wrow[p + 8];

    __syncthreads();

    // ---- stage 2: conv contribution of channel c ----
    if (tid < CONV_OUT) {
        float s = 0.f;
#pragma unroll
        for (int k = 0; k < KW; k++) s += xs[tid + k] * cw[k];
        atomicAdd(&g_conv[tid], s);
    }

    // ---- stage 3: FC -- 32 warps x 2 outputs, warp-reduced dots ----
#pragma unroll
    for (int i = 0; i < 2; i++) {
        const int d = warp * 2 + i;                      // 0..63
        const float* row = fc_w + (size_t)(c * FC + d) * W;
        float s = row[lane] * xs[lane] + row[lane + 32] * xs[lane + 32];
        if (lane < W - 64)                               // 13 tail elements
            s += row[lane + 64] * xs[lane + 64];
        s = warp_reduce(s);
        if (lane == 0) vals[d] = s + fc_b[c * FC + d];
    }
    __syncthreads();

    // ---- stage 4: g_h[j] += w2_slice[j,:] . vals ----
    {
        const float4* v4 = reinterpret_cast<const float4*>(vals);
        float s = dot4(a0, v4[p]) + dot4(a1, v4[p + 8]);
#pragma unroll
        for (int o = 4; o > 0; o >>= 1)
            s += __shfl_down_sync(0xffffffffu, s, o, 8);
        if (p == 0) atomicAdd(&g_h[j], s);
    }

    // ---- last-block election (no spinning; non-last blocks exit) ----
    __threadfence();
    __syncthreads();
    if (tid == 0)
        s_last = (atomicAdd(&g_cnt, 1u) == GRID - 1) ? 1u : 0u;
    __syncthreads();
    if (s_last == 0u) return;

    // =================== finalization (last block only) ===================
    __threadfence();                       // acquire all g_h / g_conv updates

    if (tid < CONV_OUT) {
        convv[tid]  = g_conv[tid] + conv_b[0];
        g_conv[tid] = 0.f;                 // reset for next replay
    }
    __syncthreads();

    // conv matvec: h[j] += w2[j, 9216:9284] . convv ; then relu & w3 weight
    {
        const float4* rw = reinterpret_cast<const float4*>(
            w2 + (size_t)j * CONCAT + C * FC);           // 16B-aligned
        const float4* cv = reinterpret_cast<const float4*>(convv);
        float s = dot4(rw[p], cv[p]) + dot4(rw[p + 8], cv[p + 8]);
        if (p == 0) s += dot4(rw[16], cv[16]);           // 17th float4
#pragma unroll
        for (int o = 4; o > 0; o >>= 1)
            s += __shfl_down_sync(0xffffffffu, s, o, 8);
        if (p == 0) {
            const float pre = g_h[j] + s + b2[j];
            sm_h[j] = fmaxf(pre, 0.f) * w3[j];
            g_h[j]  = 0.f;                 // reset for next replay
        }
    }
    __syncthreads();

    if (warp == 0) {
        float v = sm_h[lane] + sm_h[lane + 32]
                + sm_h[lane + 64] + sm_h[lane + 96];
        v = warp_reduce(v);
        if (lane == 0) {
            const float o2 = fmaxf(v + b3[0], 0.f);
            out[0] = 1.f / (1.f + expf(-o2));
            g_cnt  = 0u;                   // reset for next replay
        }
    }
}

// ---------------------------------------------------------------------------
extern "C" void kernel_launch(void* const* d_in, const int* in_sizes, int n_in,
                              void* d_out, int out_size) {
    const float* x      = (const float*)d_in[0];
    const float* fc_w   = (const float*)d_in[1];
    const float* fc_b   = (const float*)d_in[2];
    const float* conv_w = (const float*)d_in[3];
    const float* conv_b = (const float*)d_in[4];
    const float* w2     = (const float*)d_in[5];
    const float* b2     = (const float*)d_in[6];
    const float* w3     = (const float*)d_in[7];
    const float* b3     = (const float*)d_in[8];

    fused_kernel<<<GRID, NT>>>(x, fc_w, fc_b, conv_w, conv_b,
                               w2, b2, w3, b3, (float*)d_out);
}